// round 12
// baseline (speedup 1.0000x reference)
#include <cuda_runtime.h>
#include <cstdint>

#define NN 8192
#define NE 65536

typedef unsigned long long ull;

// ---------------- zeroed scratch blob (single memset) -----------------------
#define OFF_DEG    0
#define OFF_OUTCNT 8192
#define OFF_AGG1   16384
#define OFF_AGG2   409600
#define OFF_AGGM   671744
#define OFF_AGGL   802816
#define ZFLOATS    933888
__device__ __align__(16) float g_zbuf[ZFLOATS];

// ---------------- other scratch ---------------------------------------------
__device__ __align__(16) float g_T1[NN * 48 * 8];
__device__ __align__(16) float g_Tb1[NN * 48];
__device__ __align__(16) float g_T2[NN * 32 * 8];
__device__ __align__(16) float g_Tb2[NN * 32];
__device__ __align__(16) float g_h1[NN * 48];
__device__ __align__(16) float g_hm[NN * 16];
__device__ __align__(16) float g_hl[NN * 16];
__device__ __align__(16) float g_sea[NE * 8];   // edge_attr in src-sorted order
__device__ int   g_sdst[NE];                    // dst in src-sorted order
__device__ int   g_off[NN + 1];                 // CSR offsets by src
__device__ int   g_cursor[NN];
// bf16 hi/lo pre-packed B fragments: [kchunk][colpad][tig] uint4 {bh0,bh1,bl0,bl1}
__device__ __align__(16) uint4 g_Wb1[4 * 448 * 4];   // K=64: 4 kchunks, NCPAD=448
__device__ __align__(16) uint4 g_Wb2[3 * 320 * 4];   // K=48: 3 kchunks, NCPAD=320
__device__ float g_dinv[NN];
__device__ float g_invdeg[NN];

__device__ __forceinline__ void red_add_v4(float* p, float a, float b, float c, float d) {
    asm volatile("red.global.add.v4.f32 [%0], {%1,%2,%3,%4};"
                 :: "l"(p), "f"(a), "f"(b), "f"(c), "f"(d) : "memory");
}

// pack two floats to bf16x2: low half = lo_elem (lower k index)
__device__ __forceinline__ uint32_t pack_bf16x2(float lo_elem, float hi_elem) {
    uint32_t r;
    asm("cvt.rn.bf16x2.f32 %0, %1, %2;" : "=r"(r) : "f"(hi_elem), "f"(lo_elem));
    return r;
}

__device__ __forceinline__ void mma_bf16(float* c, const uint32_t* a, const uint32_t* b) {
    asm("mma.sync.aligned.m16n8k16.row.col.f32.bf16.bf16.f32 "
        "{%0,%1,%2,%3}, {%4,%5,%6,%7}, {%8,%9}, {%0,%1,%2,%3};"
        : "+f"(c[0]), "+f"(c[1]), "+f"(c[2]), "+f"(c[3])
        : "r"(a[0]), "r"(a[1]), "r"(a[2]), "r"(a[3]), "r"(b[0]), "r"(b[1]));
}

// split a pair (v0,v1) -> {hi packed, lo packed}
__device__ __forceinline__ uint2 split_pair(float v0, float v1) {
    uint32_t h = pack_bf16x2(v0, v1);
    float h0 = __uint_as_float(h << 16);
    float h1 = __uint_as_float(h & 0xFFFF0000u);
    uint32_t l = pack_bf16x2(v0 - h0, v1 - h1);
    return make_uint2(h, l);
}

// ---------------- prep: degree/outdeg counts + pre-packed bf16 weights ------
__device__ __forceinline__ float getw1(const float* w, const float* b, int k, int c) {
    if (c < 384) { int o = c >> 3, s = c & 7; return w[s * 3072 + k * 48 + o]; }
    if (c < 432) return b[k * 48 + (c - 384)];
    return 0.f;
}
__device__ __forceinline__ float getw2(const float* w, const float* b, int k, int c) {
    if (c < 256) { int o = c >> 3, s = c & 7; return w[s * 1536 + k * 32 + o]; }
    if (c < 288) return b[k * 32 + (c - 256)];
    return 0.f;
}

__global__ void prep_kernel(const int* __restrict__ ei,
                            const float* __restrict__ nn1w, const float* __restrict__ nn1b,
                            const float* __restrict__ nn2w, const float* __restrict__ nn2b,
                            int* __restrict__ outcnt, int* __restrict__ deg,
                            uint4* __restrict__ Wb1, uint4* __restrict__ Wb2) {
    int bx = blockIdx.x, t = threadIdx.x;
    if (bx < 256) {
        int e = bx * 256 + t;
        atomicAdd(&outcnt[ei[e]], 1);
        atomicAdd(&deg[ei[NE + e]], 1);
    } else if (bx < 284) {               // 7168 entries: layer1, NCPAD=448, 4 kchunks
        int idx = (bx - 256) * 256 + t;
        int kc = idx / 1792, rem = idx - kc * 1792;
        int col = rem >> 2, tig = rem & 3;
        int k0 = kc * 16 + tig * 2;
        uint2 p0 = split_pair(getw1(nn1w, nn1b, k0,     col), getw1(nn1w, nn1b, k0 + 1, col));
        uint2 p1 = split_pair(getw1(nn1w, nn1b, k0 + 8, col), getw1(nn1w, nn1b, k0 + 9, col));
        Wb1[idx] = make_uint4(p0.x, p1.x, p0.y, p1.y);
    } else {                              // 3840 entries: layer2, NCPAD=320, 3 kchunks
        int idx = (bx - 284) * 256 + t;
        if (idx < 3840) {
            int kc = idx / 1280, rem = idx - kc * 1280;
            int col = rem >> 2, tig = rem & 3;
            int k0 = kc * 16 + tig * 2;
            uint2 p0 = split_pair(getw2(nn2w, nn2b, k0,     col), getw2(nn2w, nn2b, k0 + 1, col));
            uint2 p1 = split_pair(getw2(nn2w, nn2b, k0 + 8, col), getw2(nn2w, nn2b, k0 + 9, col));
            Wb2[idx] = make_uint4(p0.x, p1.x, p0.y, p1.y);
        }
    }
}

// ---------------- block 0: exclusive scan of outcnt; blocks 1..8: dinv ------
__global__ void scan_dinv_kernel(const int* __restrict__ outcnt, const int* __restrict__ deg,
                                 int* __restrict__ off, int* __restrict__ cursor,
                                 float* __restrict__ dinv, float* __restrict__ invdeg) {
    int t = threadIdx.x;
    if (blockIdx.x == 0) {
        __shared__ int wsum[32];
        int base = t * 8;
        int v[8];
        int s = 0;
#pragma unroll
        for (int j = 0; j < 8; j++) { v[j] = outcnt[base + j]; s += v[j]; }
        int lane = t & 31, wid = t >> 5;
        int inc = s;
#pragma unroll
        for (int d = 1; d < 32; d <<= 1) {
            int n = __shfl_up_sync(0xFFFFFFFFu, inc, d);
            if (lane >= d) inc += n;
        }
        int excl_warp = inc - s;
        if (lane == 31) wsum[wid] = inc;
        __syncthreads();
        if (t < 32) {
            int w = wsum[t];
            int wi = w;
#pragma unroll
            for (int d = 1; d < 32; d <<= 1) {
                int n = __shfl_up_sync(0xFFFFFFFFu, wi, d);
                if (t >= d) wi += n;
            }
            wsum[t] = wi - w;
        }
        __syncthreads();
        int run = wsum[wid] + excl_warp;
#pragma unroll
        for (int j = 0; j < 8; j++) {
            off[base + j] = run;
            cursor[base + j] = run;
            run += v[j];
        }
        if (t == 1023) off[NN] = NE;
    } else {
        int n = (blockIdx.x - 1) * 1024 + t;
        float d = (float)deg[n] + 1.0f;
        dinv[n] = rsqrtf(d);
        invdeg[n] = 1.0f / d;
    }
}

// ---------------- scatter edge payloads into src-sorted order ---------------
__global__ void perm_kernel(const int* __restrict__ ei, const float* __restrict__ ea,
                            int* __restrict__ cursor,
                            int* __restrict__ sdst, float* __restrict__ sea) {
    int e = blockIdx.x * 256 + threadIdx.x;
    int s = ei[e];
    int pos = atomicAdd(&cursor[s], 1);
    sdst[pos] = ei[NE + e];
    const float4* ev = reinterpret_cast<const float4*>(ea + e * 8);
    float4* sv = reinterpret_cast<float4*>(sea + pos * 8);
    sv[0] = ev[0];
    sv[1] = ev[1];
}

// ---------------- node GEMM: bf16 3-term split, m16n8k16, 2 row-tiles/block -
// Block: 256 thr (8 warps). Per tile: 128 rows x 64 cols; warp = 16 rows.
// Ws loaded once per block, reused across both tiles.
template<int K, int CO, int NCPAD>
__global__ void __launch_bounds__(256) node_gemm_kernel(
        const float* __restrict__ X, const uint4* __restrict__ Wb,
        float* __restrict__ T, float* __restrict__ Tb) {
    constexpr int NC = CO * 9;
    constexpr int XP = K + 2;      // Xs row stride (floats), even
    constexpr int XPH = XP / 2;
    constexpr int KS = K / 16;
    extern __shared__ char smem_raw[];
    float* Xs = reinterpret_cast<float*>(smem_raw);                  // [128][XP]
    uint4* Ws = reinterpret_cast<uint4*>(smem_raw + 128 * XP * 4);   // [KS][64][4]
    int tid = threadIdx.x;
    int cbase = blockIdx.x * 64;

    // fill Ws once: one uint4 per (kchunk, col, tig)
    for (int idx = tid; idx < KS * 256; idx += 256) {
        int kc = idx >> 8, rem = idx & 255;
        Ws[idx] = Wb[kc * (NCPAD * 4) + cbase * 4 + rem];
    }

    int lane = tid & 31, wp = tid >> 5;
    int gid = lane >> 2;
    int tig = lane & 3;
    int arow = wp * 16 + gid;
    const float2* xr0 = reinterpret_cast<const float2*>(Xs) + arow * XPH + tig;
    const float2* xr1 = xr0 + 8 * XPH;

    for (int tl = 0; tl < 2; tl++) {
        int n0 = (blockIdx.y * 2 + tl) * 128;
        __syncthreads();
        // fill Xs (row-padded) with float2
        {
            const float2* X2 = reinterpret_cast<const float2*>(X + n0 * K);
            float2* Xs2 = reinterpret_cast<float2*>(Xs);
            for (int idx = tid; idx < 128 * (K / 2); idx += 256) {
                int r = idx / (K / 2), q = idx - r * (K / 2);
                Xs2[r * XPH + q] = X2[r * (K / 2) + q];
            }
        }
        __syncthreads();

        float acc[8][4];
#pragma unroll
        for (int nt = 0; nt < 8; nt++)
#pragma unroll
            for (int j = 0; j < 4; j++) acc[nt][j] = 0.f;

#pragma unroll
        for (int kc = 0; kc < KS; kc++) {
            float2 p0 = xr0[kc * 8];
            float2 p1 = xr1[kc * 8];
            float2 p2 = xr0[kc * 8 + 4];
            float2 p3 = xr1[kc * 8 + 4];
            uint32_t ah[4], al[4];
            {
                uint2 s0 = split_pair(p0.x, p0.y); ah[0] = s0.x; al[0] = s0.y;
                uint2 s1 = split_pair(p1.x, p1.y); ah[1] = s1.x; al[1] = s1.y;
                uint2 s2 = split_pair(p2.x, p2.y); ah[2] = s2.x; al[2] = s2.y;
                uint2 s3 = split_pair(p3.x, p3.y); ah[3] = s3.x; al[3] = s3.y;
            }
#pragma unroll
            for (int nt = 0; nt < 8; nt++) {
                uint4 b = Ws[(kc * 64 + nt * 8 + gid) * 4 + tig];
                uint32_t bh[2] = { b.x, b.y };
                uint32_t bl[2] = { b.z, b.w };
                mma_bf16(acc[nt], al, bh);
                mma_bf16(acc[nt], ah, bl);
                mma_bf16(acc[nt], ah, bh);
            }
        }

        int r0 = n0 + arow;
#pragma unroll
        for (int nt = 0; nt < 8; nt++) {
            int c = cbase + nt * 8 + tig * 2;
            if (c < NC) {
                if (c < CO * 8) {
                    T[r0 * (CO * 8) + c]           = acc[nt][0];
                    T[r0 * (CO * 8) + c + 1]       = acc[nt][1];
                    T[(r0 + 8) * (CO * 8) + c]     = acc[nt][2];
                    T[(r0 + 8) * (CO * 8) + c + 1] = acc[nt][3];
                } else {
                    int cc = c - CO * 8;
                    Tb[r0 * CO + cc]           = acc[nt][0];
                    Tb[r0 * CO + cc + 1]       = acc[nt][1];
                    Tb[(r0 + 8) * CO + cc]     = acc[nt][2];
                    Tb[(r0 + 8) * CO + cc + 1] = acc[nt][3];
                }
            }
        }
    }
}

// ---------------- edge NNConv: node-parallel over src-CSR -------------------
template<int CO, int TPN>
__global__ void __launch_bounds__(32 * TPN) edge_nnconv_kernel(
        const int* __restrict__ off, const int* __restrict__ sdst,
        const float* __restrict__ sea,
        const float* __restrict__ T, const float* __restrict__ Tb,
        float* __restrict__ agg) {
    int t = threadIdx.x;
    int g = t / TPN;
    int o0 = (t - g * TPN) * 4;
    int n = blockIdx.x * 32 + g;

    int beg = off[n], end = off[n + 1];
    if (beg == end) return;

    const float4* tp = reinterpret_cast<const float4*>(T + (n * CO + o0) * 8);
    float4 T0 = tp[0], T1 = tp[1], T2 = tp[2], T3 = tp[3];
    float4 T4 = tp[4], T5 = tp[5], T6 = tp[6], T7 = tp[7];
    float4 bb = *reinterpret_cast<const float4*>(Tb + n * CO + o0);

    for (int e = beg; e < end; e++) {
        int dst = sdst[e];
        const float4* eap = reinterpret_cast<const float4*>(sea + e * 8);
        float4 a0 = eap[0], a1 = eap[1];
        float r0 = bb.x + a0.x * T0.x + a0.y * T0.y + a0.z * T0.z + a0.w * T0.w
                        + a1.x * T1.x + a1.y * T1.y + a1.z * T1.z + a1.w * T1.w;
        float r1 = bb.y + a0.x * T2.x + a0.y * T2.y + a0.z * T2.z + a0.w * T2.w
                        + a1.x * T3.x + a1.y * T3.y + a1.z * T3.z + a1.w * T3.w;
        float r2 = bb.z + a0.x * T4.x + a0.y * T4.y + a0.z * T4.z + a0.w * T4.w
                        + a1.x * T5.x + a1.y * T5.y + a1.z * T5.z + a1.w * T5.w;
        float r3 = bb.w + a0.x * T6.x + a0.y * T6.y + a0.z * T6.z + a0.w * T6.w
                        + a1.x * T7.x + a1.y * T7.y + a1.z * T7.z + a1.w * T7.w;
        red_add_v4(agg + dst * CO + o0, r0, r1, r2, r3);
    }
}

// ---------------- H = relu(agg + X @ root + bias) ---------------------------
template<int K, int CO>
__global__ void root_relu_kernel(const float* __restrict__ agg, const float* __restrict__ X,
                                 const float* __restrict__ root, const float* __restrict__ bias,
                                 float* __restrict__ H) {
    constexpr int NB = 16;
    constexpr int ITEMS = NB * CO / 256;
    __shared__ float xs[NB][K];
    int n0 = blockIdx.x * NB;
    for (int idx = threadIdx.x; idx < NB * K; idx += 256)
        xs[idx / K][idx % K] = X[n0 * K + idx];
    __syncthreads();
#pragma unroll
    for (int j = 0; j < ITEMS; j++) {
        int item = threadIdx.x + j * 256;
        int nl = item / CO, o = item - nl * CO;
        float acc = agg[(n0 + nl) * CO + o] + bias[o];
#pragma unroll 4
        for (int i = 0; i < K; i++) acc += xs[nl][i] * root[i * CO + o];
        H[(n0 + nl) * CO + o] = fmaxf(acc, 0.f);
    }
}

// ---------------- fused: h2 = relu(...); hm = h2@muw; hl = h2@lsw -----------
__global__ void root2_heads_kernel(const float* __restrict__ agg, const float* __restrict__ H1,
                                   const float* __restrict__ root, const float* __restrict__ bias,
                                   const float* __restrict__ muw, const float* __restrict__ lsw,
                                   float* __restrict__ hm, float* __restrict__ hl) {
    __shared__ float xs[16][48];
    __shared__ float hs[16][32];
    int n0 = blockIdx.x * 16;
    for (int idx = threadIdx.x; idx < 16 * 48; idx += 256)
        xs[idx / 48][idx % 48] = H1[n0 * 48 + idx];
    __syncthreads();
#pragma unroll
    for (int j = 0; j < 2; j++) {
        int item = threadIdx.x + j * 256;
        int nl = item >> 5, o = item & 31;
        float acc = agg[(n0 + nl) * 32 + o] + bias[o];
#pragma unroll 4
        for (int i = 0; i < 48; i++) acc += xs[nl][i] * root[i * 32 + o];
        hs[nl][o] = fmaxf(acc, 0.f);
    }
    __syncthreads();
#pragma unroll
    for (int j = 0; j < 2; j++) {
        int item = threadIdx.x + j * 256;
        int nl = item >> 5;
        int r = item & 31;
        int head = r >> 4, o = r & 15;
        const float* W = head ? lsw : muw;
        float acc = 0.f;
#pragma unroll
        for (int i = 0; i < 32; i++) acc += hs[nl][i] * W[i * 16 + o];
        (head ? hl : hm)[(n0 + nl) * 16 + o] = acc;
    }
}

// ---------------- GCN scatter: node-parallel over src-CSR -------------------
__global__ void __launch_bounds__(256) gcn_edge_kernel(
        const int* __restrict__ off, const int* __restrict__ sdst,
        const float* __restrict__ hm, const float* __restrict__ hl,
        const float* __restrict__ dinv,
        float* __restrict__ aggm, float* __restrict__ aggl) {
    int t = threadIdx.x;
    int g = t >> 3;
    int r = t & 7;
    int head = r >> 2, q = r & 3;
    int n = blockIdx.x * 32 + g;
    int beg = off[n], end = off[n + 1];
    if (beg == end) return;

    const float* h = head ? hl : hm;
    float* a = head ? aggl : aggm;
    float4 v = *reinterpret_cast<const float4*>(h + n * 16 + q * 4);
    float ds = dinv[n];
    for (int e = beg; e < end; e++) {
        int dst = sdst[e];
        float w = ds * dinv[dst];
        red_add_v4(a + dst * 16 + q * 4, v.x * w, v.y * w, v.z * w, v.w * w);
    }
}

// ---------------- final: out = agg + h*invdeg + bias (mu then ls) -----------
__global__ void out_kernel(const float* __restrict__ aggm, const float* __restrict__ aggl,
                           const float* __restrict__ hm, const float* __restrict__ hl,
                           const float* __restrict__ invdeg, const float* __restrict__ mub,
                           const float* __restrict__ lsb, float* __restrict__ out) {
    int i4 = blockIdx.x * 256 + threadIdx.x;
    int n = i4 >> 2, q = i4 & 3;
    float iv = invdeg[n];
    float4* out4 = reinterpret_cast<float4*>(out);
    float4 am = reinterpret_cast<const float4*>(aggm)[i4];
    float4 vm = reinterpret_cast<const float4*>(hm)[i4];
    float4 bm = reinterpret_cast<const float4*>(mub)[q];
    out4[i4] = make_float4(am.x + vm.x * iv + bm.x, am.y + vm.y * iv + bm.y,
                           am.z + vm.z * iv + bm.z, am.w + vm.w * iv + bm.w);
    float4 al = reinterpret_cast<const float4*>(aggl)[i4];
    float4 vl = reinterpret_cast<const float4*>(hl)[i4];
    float4 bl = reinterpret_cast<const float4*>(lsb)[q];
    out4[32768 + i4] = make_float4(al.x + vl.x * iv + bl.x, al.y + vl.y * iv + bl.y,
                                   al.z + vl.z * iv + bl.z, al.w + vl.w * iv + bl.w);
}

// ---------------- launcher --------------------------------------------------
extern "C" void kernel_launch(void* const* d_in, const int* in_sizes, int n_in,
                              void* d_out, int out_size) {
    const float* x      = (const float*)d_in[0];
    const int*   ei     = (const int*)  d_in[1];
    const float* ea     = (const float*)d_in[2];
    const float* nn1_w  = (const float*)d_in[3];
    const float* nn1_b  = (const float*)d_in[4];
    const float* root1  = (const float*)d_in[5];
    const float* bias1  = (const float*)d_in[6];
    const float* nn2_w  = (const float*)d_in[7];
    const float* nn2_b  = (const float*)d_in[8];
    const float* root2  = (const float*)d_in[9];
    const float* bias2  = (const float*)d_in[10];
    const float* mu_w   = (const float*)d_in[11];
    const float* mu_b   = (const float*)d_in[12];
    const float* ls_w   = (const float*)d_in[13];
    const float* ls_b   = (const float*)d_in[14];
    float* out = (float*)d_out;

    void *pz, *pT1, *pTb1, *pT2, *pTb2, *ph1, *phm, *phl;
    void *pWb1, *pWb2, *pdinv, *pinvdeg, *poff, *pcur, *psdst, *psea;
    cudaGetSymbolAddress(&pz, g_zbuf);
    cudaGetSymbolAddress(&pT1, g_T1);
    cudaGetSymbolAddress(&pTb1, g_Tb1);
    cudaGetSymbolAddress(&pT2, g_T2);
    cudaGetSymbolAddress(&pTb2, g_Tb2);
    cudaGetSymbolAddress(&ph1, g_h1);
    cudaGetSymbolAddress(&phm, g_hm);
    cudaGetSymbolAddress(&phl, g_hl);
    cudaGetSymbolAddress(&pWb1, g_Wb1);
    cudaGetSymbolAddress(&pWb2, g_Wb2);
    cudaGetSymbolAddress(&pdinv, g_dinv);
    cudaGetSymbolAddress(&pinvdeg, g_invdeg);
    cudaGetSymbolAddress(&poff, g_off);
    cudaGetSymbolAddress(&pcur, g_cursor);
    cudaGetSymbolAddress(&psdst, g_sdst);
    cudaGetSymbolAddress(&psea, g_sea);

    float* zb = (float*)pz;
    int*   deg    = (int*)(zb + OFF_DEG);
    int*   outcnt = (int*)(zb + OFF_OUTCNT);
    float* agg1   = zb + OFF_AGG1;
    float* agg2   = zb + OFF_AGG2;
    float* aggm   = zb + OFF_AGGM;
    float* aggl   = zb + OFF_AGGL;

    // dynamic smem: layer1 = 128*66*4 + 4*256*16 = 33792 + 16384 = 50176
    //               layer2 = 128*50*4 + 3*256*16 = 25600 + 12288 = 37888
    cudaFuncSetAttribute(node_gemm_kernel<64, 48, 448>,
                         cudaFuncAttributeMaxDynamicSharedMemorySize, 50176);
    cudaFuncSetAttribute(node_gemm_kernel<48, 32, 320>,
                         cudaFuncAttributeMaxDynamicSharedMemorySize, 37888);

    cudaMemsetAsync(pz, 0, ZFLOATS * sizeof(float), 0);

    prep_kernel<<<299, 256>>>(ei, nn1_w, nn1_b, nn2_w, nn2_b,
                              outcnt, deg, (uint4*)pWb1, (uint4*)pWb2);
    scan_dinv_kernel<<<9, 1024>>>(outcnt, deg, (int*)poff, (int*)pcur,
                                  (float*)pdinv, (float*)pinvdeg);
    perm_kernel<<<256, 256>>>(ei, ea, (int*)pcur, (int*)psdst, (float*)psea);

    // layer 1: grid (448/64=7, 8192/256=32), 2 row-tiles per block
    node_gemm_kernel<64, 48, 448><<<dim3(7, 32), 256, 50176>>>(
        x, (uint4*)pWb1, (float*)pT1, (float*)pTb1);
    edge_nnconv_kernel<48, 12><<<NN / 32, 384>>>((int*)poff, (int*)psdst, (float*)psea,
                                                 (float*)pT1, (float*)pTb1, agg1);
    root_relu_kernel<64, 48><<<NN / 16, 256>>>(agg1, x, root1, bias1, (float*)ph1);

    // layer 2: grid (320/64=5, 32)
    node_gemm_kernel<48, 32, 320><<<dim3(5, 32), 256, 37888>>>(
        (float*)ph1, (uint4*)pWb2, (float*)pT2, (float*)pTb2);
    edge_nnconv_kernel<32, 8><<<NN / 32, 256>>>((int*)poff, (int*)psdst, (float*)psea,
                                                (float*)pT2, (float*)pTb2, agg2);
    root2_heads_kernel<<<NN / 16, 256>>>(agg2, (float*)ph1, root2, bias2,
                                         mu_w, ls_w, (float*)phm, (float*)phl);

    // GCN scatter + output
    gcn_edge_kernel<<<NN / 32, 256>>>((int*)poff, (int*)psdst, (float*)phm, (float*)phl,
                                      (float*)pdinv, aggm, aggl);
    out_kernel<<<128, 256>>>(aggm, aggl, (float*)phm, (float*)phl,
                             (float*)pinvdeg, mu_b, ls_b, out);
}

// round 13
// speedup vs baseline: 1.0718x; 1.0718x over previous
#include <cuda_runtime.h>
#include <cstdint>

#define NN 8192
#define NE 65536

typedef unsigned long long ull;

// ---------------- zeroed scratch blob -----------------------
// [0,16384): deg/outcnt (memset); [16384,933888): agg buffers (zeroed in prep)
#define OFF_DEG    0
#define OFF_OUTCNT 8192
#define OFF_AGG1   16384
#define OFF_AGG2   409600
#define OFF_AGGM   671744
#define OFF_AGGL   802816
#define ZFLOATS    933888
__device__ __align__(16) float g_zbuf[ZFLOATS];

// ---------------- other scratch ---------------------------------------------
__device__ __align__(16) float g_T1[NN * 48 * 8];
__device__ __align__(16) float g_Tb1[NN * 48];
__device__ __align__(16) float g_T2[NN * 32 * 8];
__device__ __align__(16) float g_Tb2[NN * 32];
__device__ __align__(16) float g_h1[NN * 48];
__device__ __align__(16) float g_hm[NN * 16];
__device__ __align__(16) float g_hl[NN * 16];
__device__ __align__(16) float g_sea[NE * 8];   // edge_attr in src-sorted order
__device__ int   g_sdst[NE];                    // dst in src-sorted order
__device__ int   g_off[NN + 1];                 // CSR offsets by src
__device__ int   g_cursor[NN];
// bf16 hi/lo pre-packed B fragments: [kchunk][colpad][tig] uint4 {bh0,bh1,bl0,bl1}
__device__ __align__(16) uint4 g_Wb1[4 * 448 * 4];   // K=64: 4 kchunks, NCPAD=448
__device__ __align__(16) uint4 g_Wb2[3 * 320 * 4];   // K=48: 3 kchunks, NCPAD=320
__device__ float g_dinv[NN];
__device__ float g_invdeg[NN];

__device__ __forceinline__ void red_add_v4(float* p, float a, float b, float c, float d) {
    asm volatile("red.global.add.v4.f32 [%0], {%1,%2,%3,%4};"
                 :: "l"(p), "f"(a), "f"(b), "f"(c), "f"(d) : "memory");
}

// pack two floats to bf16x2: low half = lo_elem (lower k index)
__device__ __forceinline__ uint32_t pack_bf16x2(float lo_elem, float hi_elem) {
    uint32_t r;
    asm("cvt.rn.bf16x2.f32 %0, %1, %2;" : "=r"(r) : "f"(hi_elem), "f"(lo_elem));
    return r;
}

__device__ __forceinline__ void mma_bf16(float* c, const uint32_t* a, const uint32_t* b) {
    asm("mma.sync.aligned.m16n8k16.row.col.f32.bf16.bf16.f32 "
        "{%0,%1,%2,%3}, {%4,%5,%6,%7}, {%8,%9}, {%0,%1,%2,%3};"
        : "+f"(c[0]), "+f"(c[1]), "+f"(c[2]), "+f"(c[3])
        : "r"(a[0]), "r"(a[1]), "r"(a[2]), "r"(a[3]), "r"(b[0]), "r"(b[1]));
}

// split a pair (v0,v1) -> {hi packed, lo packed}
__device__ __forceinline__ uint2 split_pair(float v0, float v1) {
    uint32_t h = pack_bf16x2(v0, v1);
    float h0 = __uint_as_float(h << 16);
    float h1 = __uint_as_float(h & 0xFFFF0000u);
    uint32_t l = pack_bf16x2(v0 - h0, v1 - h1);
    return make_uint2(h, l);
}

// ---------------- prep: counts + bf16 weights + agg zeroing -----------------
__device__ __forceinline__ float getw1(const float* w, const float* b, int k, int c) {
    if (c < 384) { int o = c >> 3, s = c & 7; return w[s * 3072 + k * 48 + o]; }
    if (c < 432) return b[k * 48 + (c - 384)];
    return 0.f;
}
__device__ __forceinline__ float getw2(const float* w, const float* b, int k, int c) {
    if (c < 256) { int o = c >> 3, s = c & 7; return w[s * 1536 + k * 32 + o]; }
    if (c < 288) return b[k * 32 + (c - 256)];
    return 0.f;
}

__global__ void prep_kernel(const int* __restrict__ ei,
                            const float* __restrict__ nn1w, const float* __restrict__ nn1b,
                            const float* __restrict__ nn2w, const float* __restrict__ nn2b,
                            int* __restrict__ outcnt, int* __restrict__ deg,
                            uint4* __restrict__ Wb1, uint4* __restrict__ Wb2,
                            float4* __restrict__ aggz) {
    int bx = blockIdx.x, t = threadIdx.x;
    if (bx < 256) {
        int e = bx * 256 + t;
        atomicAdd(&outcnt[ei[e]], 1);
        atomicAdd(&deg[ei[NE + e]], 1);
    } else if (bx < 284) {               // 7168 entries: layer1, NCPAD=448, 4 kchunks
        int idx = (bx - 256) * 256 + t;
        int kc = idx / 1792, rem = idx - kc * 1792;
        int col = rem >> 2, tig = rem & 3;
        int k0 = kc * 16 + tig * 2;
        uint2 p0 = split_pair(getw1(nn1w, nn1b, k0,     col), getw1(nn1w, nn1b, k0 + 1, col));
        uint2 p1 = split_pair(getw1(nn1w, nn1b, k0 + 8, col), getw1(nn1w, nn1b, k0 + 9, col));
        Wb1[idx] = make_uint4(p0.x, p1.x, p0.y, p1.y);
    } else if (bx < 299) {                // 3840 entries: layer2, NCPAD=320, 3 kchunks
        int idx = (bx - 284) * 256 + t;
        if (idx < 3840) {
            int kc = idx / 1280, rem = idx - kc * 1280;
            int col = rem >> 2, tig = rem & 3;
            int k0 = kc * 16 + tig * 2;
            uint2 p0 = split_pair(getw2(nn2w, nn2b, k0,     col), getw2(nn2w, nn2b, k0 + 1, col));
            uint2 p1 = split_pair(getw2(nn2w, nn2b, k0 + 8, col), getw2(nn2w, nn2b, k0 + 9, col));
            Wb2[idx] = make_uint4(p0.x, p1.x, p0.y, p1.y);
        }
    } else {                              // zero agg region: 917504 floats = 229376 float4
        int idx = (bx - 299) * 256 + t;
        if (idx < 229376) aggz[idx] = make_float4(0.f, 0.f, 0.f, 0.f);
    }
}

// ---------------- block 0: exclusive scan of outcnt; blocks 1..8: dinv ------
__global__ void scan_dinv_kernel(const int* __restrict__ outcnt, const int* __restrict__ deg,
                                 int* __restrict__ off, int* __restrict__ cursor,
                                 float* __restrict__ dinv, float* __restrict__ invdeg) {
    int t = threadIdx.x;
    if (blockIdx.x == 0) {
        __shared__ int wsum[32];
        int base = t * 8;
        int v[8];
        int s = 0;
#pragma unroll
        for (int j = 0; j < 8; j++) { v[j] = outcnt[base + j]; s += v[j]; }
        int lane = t & 31, wid = t >> 5;
        int inc = s;
#pragma unroll
        for (int d = 1; d < 32; d <<= 1) {
            int n = __shfl_up_sync(0xFFFFFFFFu, inc, d);
            if (lane >= d) inc += n;
        }
        int excl_warp = inc - s;
        if (lane == 31) wsum[wid] = inc;
        __syncthreads();
        if (t < 32) {
            int w = wsum[t];
            int wi = w;
#pragma unroll
            for (int d = 1; d < 32; d <<= 1) {
                int n = __shfl_up_sync(0xFFFFFFFFu, wi, d);
                if (t >= d) wi += n;
            }
            wsum[t] = wi - w;
        }
        __syncthreads();
        int run = wsum[wid] + excl_warp;
#pragma unroll
        for (int j = 0; j < 8; j++) {
            off[base + j] = run;
            cursor[base + j] = run;
            run += v[j];
        }
        if (t == 1023) off[NN] = NE;
    } else {
        int n = (blockIdx.x - 1) * 1024 + t;
        float d = (float)deg[n] + 1.0f;
        dinv[n] = rsqrtf(d);
        invdeg[n] = 1.0f / d;
    }
}

// ---------------- scatter edge payloads into src-sorted order ---------------
__global__ void perm_kernel(const int* __restrict__ ei, const float* __restrict__ ea,
                            int* __restrict__ cursor,
                            int* __restrict__ sdst, float* __restrict__ sea) {
    int e = blockIdx.x * 256 + threadIdx.x;
    int s = ei[e];
    int pos = atomicAdd(&cursor[s], 1);
    sdst[pos] = ei[NE + e];
    const float4* ev = reinterpret_cast<const float4*>(ea + e * 8);
    float4* sv = reinterpret_cast<float4*>(sea + pos * 8);
    sv[0] = ev[0];
    sv[1] = ev[1];
}

// ---------------- node GEMM: bf16 3-term split, two-pass n-split ------------
// Block: 256 thr (8 warps), 128 rows x 64 cols. Warp: 16 rows.
// Two passes of 4 n-tiles each -> acc=16 regs -> 4 blocks/SM, single wave.
template<int K, int CO, int NCPAD>
__global__ void __launch_bounds__(256, 4) node_gemm_kernel(
        const float* __restrict__ X, const uint4* __restrict__ Wb,
        float* __restrict__ T, float* __restrict__ Tb) {
    constexpr int NC = CO * 9;
    constexpr int XP = K + 2;      // Xs row stride (floats), even
    constexpr int XPH = XP / 2;
    constexpr int KS = K / 16;
    extern __shared__ char smem_raw[];
    float* Xs = reinterpret_cast<float*>(smem_raw);                  // [128][XP]
    uint4* Ws = reinterpret_cast<uint4*>(smem_raw + 128 * XP * 4);   // [KS][64][4]
    int tid = threadIdx.x;
    int n0 = blockIdx.y * 128;
    int cbase = blockIdx.x * 64;

    // fill Xs (row-padded) with float2
    {
        const float2* X2 = reinterpret_cast<const float2*>(X + n0 * K);
        float2* Xs2 = reinterpret_cast<float2*>(Xs);
        for (int idx = tid; idx < 128 * (K / 2); idx += 256) {
            int r = idx / (K / 2), q = idx - r * (K / 2);
            Xs2[r * XPH + q] = X2[r * (K / 2) + q];
        }
    }
    // fill Ws: one uint4 per (kchunk, col, tig)
    for (int idx = tid; idx < KS * 256; idx += 256) {
        int kc = idx >> 8, rem = idx & 255;
        Ws[idx] = Wb[kc * (NCPAD * 4) + cbase * 4 + rem];
    }
    __syncthreads();

    int lane = tid & 31, wp = tid >> 5;
    int gid = lane >> 2;
    int tig = lane & 3;
    int arow = wp * 16 + gid;
    const float2* xr0 = reinterpret_cast<const float2*>(Xs) + arow * XPH + tig;
    const float2* xr1 = xr0 + 8 * XPH;
    int r0 = n0 + arow;

#pragma unroll
    for (int p = 0; p < 2; p++) {
        float acc[4][4];
#pragma unroll
        for (int nt = 0; nt < 4; nt++)
#pragma unroll
            for (int j = 0; j < 4; j++) acc[nt][j] = 0.f;

#pragma unroll
        for (int kc = 0; kc < KS; kc++) {
            float2 p0 = xr0[kc * 8];
            float2 p1 = xr1[kc * 8];
            float2 p2 = xr0[kc * 8 + 4];
            float2 p3 = xr1[kc * 8 + 4];
            uint32_t ah[4], al[4];
            {
                uint2 s0 = split_pair(p0.x, p0.y); ah[0] = s0.x; al[0] = s0.y;
                uint2 s1 = split_pair(p1.x, p1.y); ah[1] = s1.x; al[1] = s1.y;
                uint2 s2 = split_pair(p2.x, p2.y); ah[2] = s2.x; al[2] = s2.y;
                uint2 s3 = split_pair(p3.x, p3.y); ah[3] = s3.x; al[3] = s3.y;
            }
#pragma unroll
            for (int nt = 0; nt < 4; nt++) {
                uint4 b = Ws[(kc * 64 + (p * 4 + nt) * 8 + gid) * 4 + tig];
                uint32_t bh[2] = { b.x, b.y };
                uint32_t bl[2] = { b.z, b.w };
                mma_bf16(acc[nt], al, bh);
                mma_bf16(acc[nt], ah, bl);
                mma_bf16(acc[nt], ah, bh);
            }
        }

#pragma unroll
        for (int nt = 0; nt < 4; nt++) {
            int c = cbase + (p * 4 + nt) * 8 + tig * 2;
            if (c < NC) {
                if (c < CO * 8) {
                    T[r0 * (CO * 8) + c]           = acc[nt][0];
                    T[r0 * (CO * 8) + c + 1]       = acc[nt][1];
                    T[(r0 + 8) * (CO * 8) + c]     = acc[nt][2];
                    T[(r0 + 8) * (CO * 8) + c + 1] = acc[nt][3];
                } else {
                    int cc = c - CO * 8;
                    Tb[r0 * CO + cc]           = acc[nt][0];
                    Tb[r0 * CO + cc + 1]       = acc[nt][1];
                    Tb[(r0 + 8) * CO + cc]     = acc[nt][2];
                    Tb[(r0 + 8) * CO + cc + 1] = acc[nt][3];
                }
            }
        }
    }
}

// ---------------- edge NNConv: node-parallel over src-CSR -------------------
template<int CO, int TPN>
__global__ void __launch_bounds__(32 * TPN) edge_nnconv_kernel(
        const int* __restrict__ off, const int* __restrict__ sdst,
        const float* __restrict__ sea,
        const float* __restrict__ T, const float* __restrict__ Tb,
        float* __restrict__ agg) {
    int t = threadIdx.x;
    int g = t / TPN;
    int o0 = (t - g * TPN) * 4;
    int n = blockIdx.x * 32 + g;

    int beg = off[n], end = off[n + 1];
    if (beg == end) return;

    const float4* tp = reinterpret_cast<const float4*>(T + (n * CO + o0) * 8);
    float4 T0 = tp[0], T1 = tp[1], T2 = tp[2], T3 = tp[3];
    float4 T4 = tp[4], T5 = tp[5], T6 = tp[6], T7 = tp[7];
    float4 bb = *reinterpret_cast<const float4*>(Tb + n * CO + o0);

    for (int e = beg; e < end; e++) {
        int dst = sdst[e];
        const float4* eap = reinterpret_cast<const float4*>(sea + e * 8);
        float4 a0 = eap[0], a1 = eap[1];
        float r0 = bb.x + a0.x * T0.x + a0.y * T0.y + a0.z * T0.z + a0.w * T0.w
                        + a1.x * T1.x + a1.y * T1.y + a1.z * T1.z + a1.w * T1.w;
        float r1 = bb.y + a0.x * T2.x + a0.y * T2.y + a0.z * T2.z + a0.w * T2.w
                        + a1.x * T3.x + a1.y * T3.y + a1.z * T3.z + a1.w * T3.w;
        float r2 = bb.z + a0.x * T4.x + a0.y * T4.y + a0.z * T4.z + a0.w * T4.w
                        + a1.x * T5.x + a1.y * T5.y + a1.z * T5.z + a1.w * T5.w;
        float r3 = bb.w + a0.x * T6.x + a0.y * T6.y + a0.z * T6.z + a0.w * T6.w
                        + a1.x * T7.x + a1.y * T7.y + a1.z * T7.z + a1.w * T7.w;
        red_add_v4(agg + dst * CO + o0, r0, r1, r2, r3);
    }
}

// ---------------- H = relu(agg + X @ root + bias) ---------------------------
template<int K, int CO>
__global__ void root_relu_kernel(const float* __restrict__ agg, const float* __restrict__ X,
                                 const float* __restrict__ root, const float* __restrict__ bias,
                                 float* __restrict__ H) {
    constexpr int NB = 16;
    constexpr int ITEMS = NB * CO / 256;
    __shared__ float xs[NB][K];
    int n0 = blockIdx.x * NB;
    for (int idx = threadIdx.x; idx < NB * K; idx += 256)
        xs[idx / K][idx % K] = X[n0 * K + idx];
    __syncthreads();
#pragma unroll
    for (int j = 0; j < ITEMS; j++) {
        int item = threadIdx.x + j * 256;
        int nl = item / CO, o = item - nl * CO;
        float acc = agg[(n0 + nl) * CO + o] + bias[o];
#pragma unroll 4
        for (int i = 0; i < K; i++) acc += xs[nl][i] * root[i * CO + o];
        H[(n0 + nl) * CO + o] = fmaxf(acc, 0.f);
    }
}

// ---------------- fused: h2=relu(...); hm/hl = h2@W; GCN scatter ------------
__global__ void root2_heads_gcn_kernel(
        const float* __restrict__ agg, const float* __restrict__ H1,
        const float* __restrict__ root, const float* __restrict__ bias,
        const float* __restrict__ muw, const float* __restrict__ lsw,
        const int* __restrict__ off, const int* __restrict__ sdst,
        const float* __restrict__ dinv,
        float* __restrict__ hm, float* __restrict__ hl,
        float* __restrict__ aggm, float* __restrict__ aggl) {
    __shared__ float xs[16][48];
    __shared__ float hs[16][32];
    __shared__ __align__(16) float hms[16][16];
    __shared__ __align__(16) float hls[16][16];
    int n0 = blockIdx.x * 16;
    int t = threadIdx.x;
    for (int idx = t; idx < 16 * 48; idx += 256)
        xs[idx / 48][idx % 48] = H1[n0 * 48 + idx];
    __syncthreads();
#pragma unroll
    for (int j = 0; j < 2; j++) {
        int item = t + j * 256;
        int nl = item >> 5, o = item & 31;
        float acc = agg[(n0 + nl) * 32 + o] + bias[o];
#pragma unroll 4
        for (int i = 0; i < 48; i++) acc += xs[nl][i] * root[i * 32 + o];
        hs[nl][o] = fmaxf(acc, 0.f);
    }
    __syncthreads();
#pragma unroll
    for (int j = 0; j < 2; j++) {
        int item = t + j * 256;
        int nl = item >> 5;
        int r = item & 31;
        int head = r >> 4, o = r & 15;
        const float* W = head ? lsw : muw;
        float acc = 0.f;
#pragma unroll
        for (int i = 0; i < 32; i++) acc += hs[nl][i] * W[i * 16 + o];
        (head ? hl : hm)[(n0 + nl) * 16 + o] = acc;
        (head ? hls : hms)[nl][o] = acc;
    }
    __syncthreads();

    // GCN scatter: 16 threads per node (head x quarter x edge-parity)
    int g = t >> 4;
    int r = t & 15;
    int head = r >> 3, q = (r >> 1) & 3, par = r & 1;
    int n = n0 + g;
    int beg = off[n], end = off[n + 1];
    if (beg == end) return;
    float4 v = *reinterpret_cast<const float4*>((head ? hls : hms)[g] + q * 4);
    float ds = dinv[n];
    float* a = head ? aggl : aggm;
    for (int e = beg + par; e < end; e += 2) {
        int dst = sdst[e];
        float w = ds * dinv[dst];
        red_add_v4(a + dst * 16 + q * 4, v.x * w, v.y * w, v.z * w, v.w * w);
    }
}

// ---------------- final: out = agg + h*invdeg + bias (mu then ls) -----------
__global__ void out_kernel(const float* __restrict__ aggm, const float* __restrict__ aggl,
                           const float* __restrict__ hm, const float* __restrict__ hl,
                           const float* __restrict__ invdeg, const float* __restrict__ mub,
                           const float* __restrict__ lsb, float* __restrict__ out) {
    int i4 = blockIdx.x * 256 + threadIdx.x;
    int n = i4 >> 2, q = i4 & 3;
    float iv = invdeg[n];
    float4* out4 = reinterpret_cast<float4*>(out);
    float4 am = reinterpret_cast<const float4*>(aggm)[i4];
    float4 vm = reinterpret_cast<const float4*>(hm)[i4];
    float4 bm = reinterpret_cast<const float4*>(mub)[q];
    out4[i4] = make_float4(am.x + vm.x * iv + bm.x, am.y + vm.y * iv + bm.y,
                           am.z + vm.z * iv + bm.z, am.w + vm.w * iv + bm.w);
    float4 al = reinterpret_cast<const float4*>(aggl)[i4];
    float4 vl = reinterpret_cast<const float4*>(hl)[i4];
    float4 bl = reinterpret_cast<const float4*>(lsb)[q];
    out4[32768 + i4] = make_float4(al.x + vl.x * iv + bl.x, al.y + vl.y * iv + bl.y,
                                   al.z + vl.z * iv + bl.z, al.w + vl.w * iv + bl.w);
}

// ---------------- launcher --------------------------------------------------
extern "C" void kernel_launch(void* const* d_in, const int* in_sizes, int n_in,
                              void* d_out, int out_size) {
    const float* x      = (const float*)d_in[0];
    const int*   ei     = (const int*)  d_in[1];
    const float* ea     = (const float*)d_in[2];
    const float* nn1_w  = (const float*)d_in[3];
    const float* nn1_b  = (const float*)d_in[4];
    const float* root1  = (const float*)d_in[5];
    const float* bias1  = (const float*)d_in[6];
    const float* nn2_w  = (const float*)d_in[7];
    const float* nn2_b  = (const float*)d_in[8];
    const float* root2  = (const float*)d_in[9];
    const float* bias2  = (const float*)d_in[10];
    const float* mu_w   = (const float*)d_in[11];
    const float* mu_b   = (const float*)d_in[12];
    const float* ls_w   = (const float*)d_in[13];
    const float* ls_b   = (const float*)d_in[14];
    float* out = (float*)d_out;

    void *pz, *pT1, *pTb1, *pT2, *pTb2, *ph1, *phm, *phl;
    void *pWb1, *pWb2, *pdinv, *pinvdeg, *poff, *pcur, *psdst, *psea;
    cudaGetSymbolAddress(&pz, g_zbuf);
    cudaGetSymbolAddress(&pT1, g_T1);
    cudaGetSymbolAddress(&pTb1, g_Tb1);
    cudaGetSymbolAddress(&pT2, g_T2);
    cudaGetSymbolAddress(&pTb2, g_Tb2);
    cudaGetSymbolAddress(&ph1, g_h1);
    cudaGetSymbolAddress(&phm, g_hm);
    cudaGetSymbolAddress(&phl, g_hl);
    cudaGetSymbolAddress(&pWb1, g_Wb1);
    cudaGetSymbolAddress(&pWb2, g_Wb2);
    cudaGetSymbolAddress(&pdinv, g_dinv);
    cudaGetSymbolAddress(&pinvdeg, g_invdeg);
    cudaGetSymbolAddress(&poff, g_off);
    cudaGetSymbolAddress(&pcur, g_cursor);
    cudaGetSymbolAddress(&psdst, g_sdst);
    cudaGetSymbolAddress(&psea, g_sea);

    float* zb = (float*)pz;
    int*   deg    = (int*)(zb + OFF_DEG);
    int*   outcnt = (int*)(zb + OFF_OUTCNT);
    float* agg1   = zb + OFF_AGG1;
    float* agg2   = zb + OFF_AGG2;
    float* aggm   = zb + OFF_AGGM;
    float* aggl   = zb + OFF_AGGL;

    // dynamic smem: layer1 = 128*66*4 + 4*256*16 = 33792 + 16384 = 50176
    //               layer2 = 128*50*4 + 3*256*16 = 25600 + 12288 = 37888
    cudaFuncSetAttribute(node_gemm_kernel<64, 48, 448>,
                         cudaFuncAttributeMaxDynamicSharedMemorySize, 50176);
    cudaFuncSetAttribute(node_gemm_kernel<48, 32, 320>,
                         cudaFuncAttributeMaxDynamicSharedMemorySize, 37888);

    // only counters need pre-zeroing; agg region is zeroed inside prep
    cudaMemsetAsync(pz, 0, 16384 * sizeof(float), 0);

    // 299 blocks (counts+weights) + 896 blocks (agg zero)
    prep_kernel<<<1195, 256>>>(ei, nn1_w, nn1_b, nn2_w, nn2_b,
                               outcnt, deg, (uint4*)pWb1, (uint4*)pWb2,
                               (float4*)agg1);
    scan_dinv_kernel<<<9, 1024>>>(outcnt, deg, (int*)poff, (int*)pcur,
                                  (float*)pdinv, (float*)pinvdeg);
    perm_kernel<<<256, 256>>>(ei, ea, (int*)pcur, (int*)psdst, (float*)psea);

    // layer 1: grid (448/64=7, 8192/128=64)
    node_gemm_kernel<64, 48, 448><<<dim3(7, 64), 256, 50176>>>(
        x, (uint4*)pWb1, (float*)pT1, (float*)pTb1);
    edge_nnconv_kernel<48, 12><<<NN / 32, 384>>>((int*)poff, (int*)psdst, (float*)psea,
                                                 (float*)pT1, (float*)pTb1, agg1);
    root_relu_kernel<64, 48><<<NN / 16, 256>>>(agg1, x, root1, bias1, (float*)ph1);

    // layer 2: grid (320/64=5, 64)
    node_gemm_kernel<48, 32, 320><<<dim3(5, 64), 256, 37888>>>(
        (float*)ph1, (uint4*)pWb2, (float*)pT2, (float*)pTb2);
    edge_nnconv_kernel<32, 8><<<NN / 32, 256>>>((int*)poff, (int*)psdst, (float*)psea,
                                                (float*)pT2, (float*)pTb2, agg2);
    root2_heads_gcn_kernel<<<NN / 16, 256>>>(agg2, (float*)ph1, root2, bias2,
                                             mu_w, ls_w, (int*)poff, (int*)psdst,
                                             (float*)pdinv,
                                             (float*)phm, (float*)phl, aggm, aggl);

    out_kernel<<<128, 256>>>(aggm, aggl, (float*)phm, (float*)phl,
                             (float*)pinvdeg, mu_b, ls_b, out);
}

// round 14
// speedup vs baseline: 1.1794x; 1.1004x over previous
#include <cuda_runtime.h>
#include <cstdint>

#define NN 8192
#define NE 65536

typedef unsigned long long ull;

// ---------------- zeroed scratch blob -----------------------
// [0,16384): deg/outcnt (memset); [16384,933888): agg buffers (zeroed in prep)
#define OFF_DEG    0
#define OFF_OUTCNT 8192
#define OFF_AGG1   16384
#define OFF_AGG2   409600
#define OFF_AGGM   671744
#define OFF_AGGL   802816
#define ZFLOATS    933888
__device__ __align__(16) float g_zbuf[ZFLOATS];

// ---------------- other scratch ---------------------------------------------
__device__ __align__(16) float g_T1[NN * 48 * 8];
__device__ __align__(16) float g_Tb1[NN * 48];
__device__ __align__(16) float g_T2[NN * 32 * 8];
__device__ __align__(16) float g_Tb2[NN * 32];
__device__ __align__(16) float g_h1[NN * 48];
__device__ __align__(16) float g_hm[NN * 16];
__device__ __align__(16) float g_hl[NN * 16];
__device__ __align__(16) float g_sea[NE * 8];   // edge_attr in src-sorted order
__device__ int   g_sdst[NE];                    // dst in src-sorted order
__device__ int   g_off[NN + 1];                 // CSR offsets by src
__device__ int   g_cursor[NN];
// bf16 hi/lo pre-packed B fragments: [kchunk][colpad][tig] uint4 {bh0,bh1,bl0,bl1}
__device__ __align__(16) uint4 g_Wb1[4 * 448 * 4];   // K=64: 4 kchunks, NCPAD=448
__device__ __align__(16) uint4 g_Wb2[3 * 320 * 4];   // K=48: 3 kchunks, NCPAD=320
__device__ float g_dinv[NN];
__device__ float g_invdeg[NN];

__device__ __forceinline__ void red_add_v4(float* p, float a, float b, float c, float d) {
    asm volatile("red.global.add.v4.f32 [%0], {%1,%2,%3,%4};"
                 :: "l"(p), "f"(a), "f"(b), "f"(c), "f"(d) : "memory");
}

// pack two floats to bf16x2: low half = lo_elem (lower k index)
__device__ __forceinline__ uint32_t pack_bf16x2(float lo_elem, float hi_elem) {
    uint32_t r;
    asm("cvt.rn.bf16x2.f32 %0, %1, %2;" : "=r"(r) : "f"(hi_elem), "f"(lo_elem));
    return r;
}

__device__ __forceinline__ void mma_bf16(float* c, const uint32_t* a, const uint32_t* b) {
    asm("mma.sync.aligned.m16n8k16.row.col.f32.bf16.bf16.f32 "
        "{%0,%1,%2,%3}, {%4,%5,%6,%7}, {%8,%9}, {%0,%1,%2,%3};"
        : "+f"(c[0]), "+f"(c[1]), "+f"(c[2]), "+f"(c[3])
        : "r"(a[0]), "r"(a[1]), "r"(a[2]), "r"(a[3]), "r"(b[0]), "r"(b[1]));
}

// split a pair (v0,v1) -> {hi packed, lo packed}
__device__ __forceinline__ uint2 split_pair(float v0, float v1) {
    uint32_t h = pack_bf16x2(v0, v1);
    float h0 = __uint_as_float(h << 16);
    float h1 = __uint_as_float(h & 0xFFFF0000u);
    uint32_t l = pack_bf16x2(v0 - h0, v1 - h1);
    return make_uint2(h, l);
}

// ---------------- prep: counts + bf16 weights + agg zeroing -----------------
__device__ __forceinline__ float getw1(const float* w, const float* b, int k, int c) {
    if (c < 384) { int o = c >> 3, s = c & 7; return w[s * 3072 + k * 48 + o]; }
    if (c < 432) return b[k * 48 + (c - 384)];
    return 0.f;
}
__device__ __forceinline__ float getw2(const float* w, const float* b, int k, int c) {
    if (c < 256) { int o = c >> 3, s = c & 7; return w[s * 1536 + k * 32 + o]; }
    if (c < 288) return b[k * 32 + (c - 256)];
    return 0.f;
}

__global__ void prep_kernel(const int* __restrict__ ei,
                            const float* __restrict__ nn1w, const float* __restrict__ nn1b,
                            const float* __restrict__ nn2w, const float* __restrict__ nn2b,
                            int* __restrict__ outcnt, int* __restrict__ deg,
                            uint4* __restrict__ Wb1, uint4* __restrict__ Wb2,
                            float4* __restrict__ aggz) {
    int bx = blockIdx.x, t = threadIdx.x;
    if (bx < 256) {
        int e = bx * 256 + t;
        atomicAdd(&outcnt[ei[e]], 1);
        atomicAdd(&deg[ei[NE + e]], 1);
    } else if (bx < 284) {               // 7168 entries: layer1, NCPAD=448, 4 kchunks
        int idx = (bx - 256) * 256 + t;
        int kc = idx / 1792, rem = idx - kc * 1792;
        int col = rem >> 2, tig = rem & 3;
        int k0 = kc * 16 + tig * 2;
        uint2 p0 = split_pair(getw1(nn1w, nn1b, k0,     col), getw1(nn1w, nn1b, k0 + 1, col));
        uint2 p1 = split_pair(getw1(nn1w, nn1b, k0 + 8, col), getw1(nn1w, nn1b, k0 + 9, col));
        Wb1[idx] = make_uint4(p0.x, p1.x, p0.y, p1.y);
    } else if (bx < 299) {                // 3840 entries: layer2, NCPAD=320, 3 kchunks
        int idx = (bx - 284) * 256 + t;
        if (idx < 3840) {
            int kc = idx / 1280, rem = idx - kc * 1280;
            int col = rem >> 2, tig = rem & 3;
            int k0 = kc * 16 + tig * 2;
            uint2 p0 = split_pair(getw2(nn2w, nn2b, k0,     col), getw2(nn2w, nn2b, k0 + 1, col));
            uint2 p1 = split_pair(getw2(nn2w, nn2b, k0 + 8, col), getw2(nn2w, nn2b, k0 + 9, col));
            Wb2[idx] = make_uint4(p0.x, p1.x, p0.y, p1.y);
        }
    } else {                              // zero agg region: 917504 floats = 229376 float4
        int idx = (bx - 299) * 256 + t;
        if (idx < 229376) aggz[idx] = make_float4(0.f, 0.f, 0.f, 0.f);
    }
}

// ---------------- block 0: exclusive scan of outcnt; blocks 1..8: dinv ------
__global__ void scan_dinv_kernel(const int* __restrict__ outcnt, const int* __restrict__ deg,
                                 int* __restrict__ off, int* __restrict__ cursor,
                                 float* __restrict__ dinv, float* __restrict__ invdeg) {
    int t = threadIdx.x;
    if (blockIdx.x == 0) {
        __shared__ int wsum[32];
        int base = t * 8;
        int v[8];
        int s = 0;
#pragma unroll
        for (int j = 0; j < 8; j++) { v[j] = outcnt[base + j]; s += v[j]; }
        int lane = t & 31, wid = t >> 5;
        int inc = s;
#pragma unroll
        for (int d = 1; d < 32; d <<= 1) {
            int n = __shfl_up_sync(0xFFFFFFFFu, inc, d);
            if (lane >= d) inc += n;
        }
        int excl_warp = inc - s;
        if (lane == 31) wsum[wid] = inc;
        __syncthreads();
        if (t < 32) {
            int w = wsum[t];
            int wi = w;
#pragma unroll
            for (int d = 1; d < 32; d <<= 1) {
                int n = __shfl_up_sync(0xFFFFFFFFu, wi, d);
                if (t >= d) wi += n;
            }
            wsum[t] = wi - w;
        }
        __syncthreads();
        int run = wsum[wid] + excl_warp;
#pragma unroll
        for (int j = 0; j < 8; j++) {
            off[base + j] = run;
            cursor[base + j] = run;
            run += v[j];
        }
        if (t == 1023) off[NN] = NE;
    } else {
        int n = (blockIdx.x - 1) * 1024 + t;
        float d = (float)deg[n] + 1.0f;
        dinv[n] = rsqrtf(d);
        invdeg[n] = 1.0f / d;
    }
}

// ---------------- scatter edge payloads into src-sorted order ---------------
__global__ void perm_kernel(const int* __restrict__ ei, const float* __restrict__ ea,
                            int* __restrict__ cursor,
                            int* __restrict__ sdst, float* __restrict__ sea) {
    int e = blockIdx.x * 256 + threadIdx.x;
    int s = ei[e];
    int pos = atomicAdd(&cursor[s], 1);
    sdst[pos] = ei[NE + e];
    const float4* ev = reinterpret_cast<const float4*>(ea + e * 8);
    float4* sv = reinterpret_cast<float4*>(sea + pos * 8);
    sv[0] = ev[0];
    sv[1] = ev[1];
}

// ---------------- node GEMM: bf16 3-term split, A direct from gmem ----------
// Block: 256 thr (8 warps), 128 rows x 64 cols. Warp: 16 rows. No Xs smem:
// A fragments loaded as coalesced-per-row float2 LDGs (X is L2-resident).
// Stores widened to float2 (full 32B sectors per warp-row).
template<int K, int CO, int NCPAD>
__global__ void __launch_bounds__(256) node_gemm_kernel(
        const float* __restrict__ X, const uint4* __restrict__ Wb,
        float* __restrict__ T, float* __restrict__ Tb) {
    constexpr int NC = CO * 9;
    constexpr int KS = K / 16;
    constexpr int KH = K / 2;
    __shared__ uint4 Ws[KS * 256];
    int tid = threadIdx.x;
    int n0 = blockIdx.y * 128;
    int cbase = blockIdx.x * 64;

    // fill Ws: one uint4 per (kchunk, col, tig)
    for (int idx = tid; idx < KS * 256; idx += 256) {
        int kc = idx >> 8, rem = idx & 255;
        Ws[idx] = Wb[kc * (NCPAD * 4) + cbase * 4 + rem];
    }
    __syncthreads();

    int lane = tid & 31, wp = tid >> 5;
    int gid = lane >> 2;
    int tig = lane & 3;
    int r0 = n0 + wp * 16 + gid;

    const float2* XA = reinterpret_cast<const float2*>(X) + r0 * KH + tig;
    const float2* XB = XA + 8 * KH;

    float acc[8][4];
#pragma unroll
    for (int nt = 0; nt < 8; nt++)
#pragma unroll
        for (int j = 0; j < 4; j++) acc[nt][j] = 0.f;

#pragma unroll
    for (int kc = 0; kc < KS; kc++) {
        float2 p0 = __ldg(XA + kc * 8);
        float2 p1 = __ldg(XB + kc * 8);
        float2 p2 = __ldg(XA + kc * 8 + 4);
        float2 p3 = __ldg(XB + kc * 8 + 4);
        uint32_t ah[4], al[4];
        {
            uint2 s0 = split_pair(p0.x, p0.y); ah[0] = s0.x; al[0] = s0.y;
            uint2 s1 = split_pair(p1.x, p1.y); ah[1] = s1.x; al[1] = s1.y;
            uint2 s2 = split_pair(p2.x, p2.y); ah[2] = s2.x; al[2] = s2.y;
            uint2 s3 = split_pair(p3.x, p3.y); ah[3] = s3.x; al[3] = s3.y;
        }
#pragma unroll
        for (int nt = 0; nt < 8; nt++) {
            uint4 b = Ws[(kc * 64 + nt * 8 + gid) * 4 + tig];
            uint32_t bh[2] = { b.x, b.y };
            uint32_t bl[2] = { b.z, b.w };
            mma_bf16(acc[nt], al, bh);
            mma_bf16(acc[nt], ah, bl);
            mma_bf16(acc[nt], ah, bh);
        }
    }

#pragma unroll
    for (int nt = 0; nt < 8; nt++) {
        int c = cbase + nt * 8 + tig * 2;
        if (c < NC) {
            float2 v01 = make_float2(acc[nt][0], acc[nt][1]);
            float2 v23 = make_float2(acc[nt][2], acc[nt][3]);
            if (c < CO * 8) {
                *reinterpret_cast<float2*>(T + r0 * (CO * 8) + c)       = v01;
                *reinterpret_cast<float2*>(T + (r0 + 8) * (CO * 8) + c) = v23;
            } else {
                int cc = c - CO * 8;
                *reinterpret_cast<float2*>(Tb + r0 * CO + cc)       = v01;
                *reinterpret_cast<float2*>(Tb + (r0 + 8) * CO + cc) = v23;
            }
        }
    }
}

// ---------------- edge NNConv: node-parallel over src-CSR -------------------
template<int CO, int TPN>
__global__ void __launch_bounds__(32 * TPN) edge_nnconv_kernel(
        const int* __restrict__ off, const int* __restrict__ sdst,
        const float* __restrict__ sea,
        const float* __restrict__ T, const float* __restrict__ Tb,
        float* __restrict__ agg) {
    int t = threadIdx.x;
    int g = t / TPN;
    int o0 = (t - g * TPN) * 4;
    int n = blockIdx.x * 32 + g;

    int beg = off[n], end = off[n + 1];
    if (beg == end) return;

    const float4* tp = reinterpret_cast<const float4*>(T + (n * CO + o0) * 8);
    float4 T0 = tp[0], T1 = tp[1], T2 = tp[2], T3 = tp[3];
    float4 T4 = tp[4], T5 = tp[5], T6 = tp[6], T7 = tp[7];
    float4 bb = *reinterpret_cast<const float4*>(Tb + n * CO + o0);

    for (int e = beg; e < end; e++) {
        int dst = sdst[e];
        const float4* eap = reinterpret_cast<const float4*>(sea + e * 8);
        float4 a0 = eap[0], a1 = eap[1];
        float r0 = bb.x + a0.x * T0.x + a0.y * T0.y + a0.z * T0.z + a0.w * T0.w
                        + a1.x * T1.x + a1.y * T1.y + a1.z * T1.z + a1.w * T1.w;
        float r1 = bb.y + a0.x * T2.x + a0.y * T2.y + a0.z * T2.z + a0.w * T2.w
                        + a1.x * T3.x + a1.y * T3.y + a1.z * T3.z + a1.w * T3.w;
        float r2 = bb.z + a0.x * T4.x + a0.y * T4.y + a0.z * T4.z + a0.w * T4.w
                        + a1.x * T5.x + a1.y * T5.y + a1.z * T5.z + a1.w * T5.w;
        float r3 = bb.w + a0.x * T6.x + a0.y * T6.y + a0.z * T6.z + a0.w * T6.w
                        + a1.x * T7.x + a1.y * T7.y + a1.z * T7.z + a1.w * T7.w;
        red_add_v4(agg + dst * CO + o0, r0, r1, r2, r3);
    }
}

// ---------------- H = relu(agg + X @ root + bias) ---------------------------
template<int K, int CO>
__global__ void root_relu_kernel(const float* __restrict__ agg, const float* __restrict__ X,
                                 const float* __restrict__ root, const float* __restrict__ bias,
                                 float* __restrict__ H) {
    constexpr int NB = 16;
    constexpr int ITEMS = NB * CO / 256;
    __shared__ float xs[NB][K];
    int n0 = blockIdx.x * NB;
    for (int idx = threadIdx.x; idx < NB * K; idx += 256)
        xs[idx / K][idx % K] = X[n0 * K + idx];
    __syncthreads();
#pragma unroll
    for (int j = 0; j < ITEMS; j++) {
        int item = threadIdx.x + j * 256;
        int nl = item / CO, o = item - nl * CO;
        float acc = agg[(n0 + nl) * CO + o] + bias[o];
#pragma unroll 4
        for (int i = 0; i < K; i++) acc += xs[nl][i] * root[i * CO + o];
        H[(n0 + nl) * CO + o] = fmaxf(acc, 0.f);
    }
}

// ---------------- fused: h2=relu(...); hm/hl = h2@W; GCN scatter ------------
__global__ void root2_heads_gcn_kernel(
        const float* __restrict__ agg, const float* __restrict__ H1,
        const float* __restrict__ root, const float* __restrict__ bias,
        const float* __restrict__ muw, const float* __restrict__ lsw,
        const int* __restrict__ off, const int* __restrict__ sdst,
        const float* __restrict__ dinv,
        float* __restrict__ hm, float* __restrict__ hl,
        float* __restrict__ aggm, float* __restrict__ aggl) {
    __shared__ float xs[16][48];
    __shared__ float hs[16][32];
    __shared__ __align__(16) float hms[16][16];
    __shared__ __align__(16) float hls[16][16];
    int n0 = blockIdx.x * 16;
    int t = threadIdx.x;
    for (int idx = t; idx < 16 * 48; idx += 256)
        xs[idx / 48][idx % 48] = H1[n0 * 48 + idx];
    __syncthreads();
#pragma unroll
    for (int j = 0; j < 2; j++) {
        int item = t + j * 256;
        int nl = item >> 5, o = item & 31;
        float acc = agg[(n0 + nl) * 32 + o] + bias[o];
#pragma unroll 4
        for (int i = 0; i < 48; i++) acc += xs[nl][i] * root[i * 32 + o];
        hs[nl][o] = fmaxf(acc, 0.f);
    }
    __syncthreads();
#pragma unroll
    for (int j = 0; j < 2; j++) {
        int item = t + j * 256;
        int nl = item >> 5;
        int r = item & 31;
        int head = r >> 4, o = r & 15;
        const float* W = head ? lsw : muw;
        float acc = 0.f;
#pragma unroll
        for (int i = 0; i < 32; i++) acc += hs[nl][i] * W[i * 16 + o];
        (head ? hl : hm)[(n0 + nl) * 16 + o] = acc;
        (head ? hls : hms)[nl][o] = acc;
    }
    __syncthreads();

    // GCN scatter: 16 threads per node (head x quarter x edge-parity)
    int g = t >> 4;
    int r = t & 15;
    int head = r >> 3, q = (r >> 1) & 3, par = r & 1;
    int n = n0 + g;
    int beg = off[n], end = off[n + 1];
    if (beg == end) return;
    float4 v = *reinterpret_cast<const float4*>((head ? hls : hms)[g] + q * 4);
    float ds = dinv[n];
    float* a = head ? aggl : aggm;
    for (int e = beg + par; e < end; e += 2) {
        int dst = sdst[e];
        float w = ds * dinv[dst];
        red_add_v4(a + dst * 16 + q * 4, v.x * w, v.y * w, v.z * w, v.w * w);
    }
}

// ---------------- final: out = agg + h*invdeg + bias (mu then ls) -----------
__global__ void out_kernel(const float* __restrict__ aggm, const float* __restrict__ aggl,
                           const float* __restrict__ hm, const float* __restrict__ hl,
                           const float* __restrict__ invdeg, const float* __restrict__ mub,
                           const float* __restrict__ lsb, float* __restrict__ out) {
    int i4 = blockIdx.x * 256 + threadIdx.x;
    int n = i4 >> 2, q = i4 & 3;
    float iv = invdeg[n];
    float4* out4 = reinterpret_cast<float4*>(out);
    float4 am = reinterpret_cast<const float4*>(aggm)[i4];
    float4 vm = reinterpret_cast<const float4*>(hm)[i4];
    float4 bm = reinterpret_cast<const float4*>(mub)[q];
    out4[i4] = make_float4(am.x + vm.x * iv + bm.x, am.y + vm.y * iv + bm.y,
                           am.z + vm.z * iv + bm.z, am.w + vm.w * iv + bm.w);
    float4 al = reinterpret_cast<const float4*>(aggl)[i4];
    float4 vl = reinterpret_cast<const float4*>(hl)[i4];
    float4 bl = reinterpret_cast<const float4*>(lsb)[q];
    out4[32768 + i4] = make_float4(al.x + vl.x * iv + bl.x, al.y + vl.y * iv + bl.y,
                                   al.z + vl.z * iv + bl.z, al.w + vl.w * iv + bl.w);
}

// ---------------- launcher --------------------------------------------------
extern "C" void kernel_launch(void* const* d_in, const int* in_sizes, int n_in,
                              void* d_out, int out_size) {
    const float* x      = (const float*)d_in[0];
    const int*   ei     = (const int*)  d_in[1];
    const float* ea     = (const float*)d_in[2];
    const float* nn1_w  = (const float*)d_in[3];
    const float* nn1_b  = (const float*)d_in[4];
    const float* root1  = (const float*)d_in[5];
    const float* bias1  = (const float*)d_in[6];
    const float* nn2_w  = (const float*)d_in[7];
    const float* nn2_b  = (const float*)d_in[8];
    const float* root2  = (const float*)d_in[9];
    const float* bias2  = (const float*)d_in[10];
    const float* mu_w   = (const float*)d_in[11];
    const float* mu_b   = (const float*)d_in[12];
    const float* ls_w   = (const float*)d_in[13];
    const float* ls_b   = (const float*)d_in[14];
    float* out = (float*)d_out;

    void *pz, *pT1, *pTb1, *pT2, *pTb2, *ph1, *phm, *phl;
    void *pWb1, *pWb2, *pdinv, *pinvdeg, *poff, *pcur, *psdst, *psea;
    cudaGetSymbolAddress(&pz, g_zbuf);
    cudaGetSymbolAddress(&pT1, g_T1);
    cudaGetSymbolAddress(&pTb1, g_Tb1);
    cudaGetSymbolAddress(&pT2, g_T2);
    cudaGetSymbolAddress(&pTb2, g_Tb2);
    cudaGetSymbolAddress(&ph1, g_h1);
    cudaGetSymbolAddress(&phm, g_hm);
    cudaGetSymbolAddress(&phl, g_hl);
    cudaGetSymbolAddress(&pWb1, g_Wb1);
    cudaGetSymbolAddress(&pWb2, g_Wb2);
    cudaGetSymbolAddress(&pdinv, g_dinv);
    cudaGetSymbolAddress(&pinvdeg, g_invdeg);
    cudaGetSymbolAddress(&poff, g_off);
    cudaGetSymbolAddress(&pcur, g_cursor);
    cudaGetSymbolAddress(&psdst, g_sdst);
    cudaGetSymbolAddress(&psea, g_sea);

    float* zb = (float*)pz;
    int*   deg    = (int*)(zb + OFF_DEG);
    int*   outcnt = (int*)(zb + OFF_OUTCNT);
    float* agg1   = zb + OFF_AGG1;
    float* agg2   = zb + OFF_AGG2;
    float* aggm   = zb + OFF_AGGM;
    float* aggl   = zb + OFF_AGGL;

    // only counters need pre-zeroing; agg region is zeroed inside prep
    cudaMemsetAsync(pz, 0, 16384 * sizeof(float), 0);

    // 299 blocks (counts+weights) + 896 blocks (agg zero)
    prep_kernel<<<1195, 256>>>(ei, nn1_w, nn1_b, nn2_w, nn2_b,
                               outcnt, deg, (uint4*)pWb1, (uint4*)pWb2,
                               (float4*)agg1);
    scan_dinv_kernel<<<9, 1024>>>(outcnt, deg, (int*)poff, (int*)pcur,
                                  (float*)pdinv, (float*)pinvdeg);
    perm_kernel<<<256, 256>>>(ei, ea, (int*)pcur, (int*)psdst, (float*)psea);

    // layer 1: grid (448/64=7, 8192/128=64)
    node_gemm_kernel<64, 48, 448><<<dim3(7, 64), 256>>>(
        x, (uint4*)pWb1, (float*)pT1, (float*)pTb1);
    edge_nnconv_kernel<48, 12><<<NN / 32, 384>>>((int*)poff, (int*)psdst, (float*)psea,
                                                 (float*)pT1, (float*)pTb1, agg1);
    root_relu_kernel<64, 48><<<NN / 16, 256>>>(agg1, x, root1, bias1, (float*)ph1);

    // layer 2: grid (320/64=5, 64)
    node_gemm_kernel<48, 32, 320><<<dim3(5, 64), 256>>>(
        (float*)ph1, (uint4*)pWb2, (float*)pT2, (float*)pTb2);
    edge_nnconv_kernel<32, 8><<<NN / 32, 256>>>((int*)poff, (int*)psdst, (float*)psea,
                                                (float*)pT2, (float*)pTb2, agg2);
    root2_heads_gcn_kernel<<<NN / 16, 256>>>(agg2, (float*)ph1, root2, bias2,
                                             mu_w, ls_w, (int*)poff, (int*)psdst,
                                             (float*)pdinv,
                                             (float*)phm, (float*)phl, aggm, aggl);

    out_kernel<<<128, 256>>>(aggm, aggl, (float*)phm, (float*)phl,
                             (float*)pinvdeg, mu_b, ls_b, out);
}